// round 16
// baseline (speedup 1.0000x reference)
#include <cuda_runtime.h>
#include <cuda_fp16.h>
#include <cstdint>

// Problem constants
#define BB   4
#define SS   2048
#define DD   1024
#define HH   16
#define HD   64
#define BS   (BB*SS)        // 8192

__device__ __forceinline__ uint32_t smem_u32(const void* p) {
    uint32_t a;
    asm("{ .reg .u64 t; cvta.to.shared.u64 t, %1; cvt.u32.u64 %0, t; }" : "=r"(a) : "l"(p));
    return a;
}
__device__ __forceinline__ void cp16(uint32_t dst, const void* src) {
    asm volatile("cp.async.cg.shared.global [%0], [%1], 16;" :: "r"(dst), "l"(src));
}
#define CP_COMMIT() asm volatile("cp.async.commit_group;" ::: "memory")
#define CP_WAIT0()  asm volatile("cp.async.wait_group 0;" ::: "memory")

// 0.125 * log2(e): folded into Q at the GEMM1 epilogue
#define QSCALE 0.18033688011112042f

// ---------------------------------------------------------------------------
// Scratch (device globals)
// ---------------------------------------------------------------------------
__device__ __half g_x16[(size_t)BS * DD];      // x fp16
__device__ __half g_w1[(size_t)DD * (3*DD)];   // W_in  [1024,3072] fp16 row-major
__device__ __half g_w2[(size_t)DD * DD];       // W_out [1024,1024] fp16 row-major
__device__ __half g_ph[(size_t)BS * 3 * DD];   // proj (k|q|v) fp16, q pre-scaled
__device__ __half g_ah[(size_t)BS * DD];       // attention out fp16

// ---------------------------------------------------------------------------
// Fused prep: convert x, W_in, W_out to fp16 in one launch.
// ---------------------------------------------------------------------------
#define N4X  (BS * DD / 4)
#define N4W1 (DD * 3 * DD / 4)
#define N4W2 (DD * DD / 4)
#define N4ALL (N4X + N4W1 + N4W2)

__global__ __launch_bounds__(256) void conv_all(
    const float* __restrict__ x, const float* __restrict__ W1,
    const float* __restrict__ W2,
    __half* __restrict__ x16, __half* __restrict__ w1, __half* __restrict__ w2)
{
    int i = blockIdx.x * 256 + threadIdx.x;
    if (i >= N4ALL) return;
    const float* src;
    __half* dst;
    int j;
    if (i < N4X)              { src = x;  dst = x16; j = i; }
    else if (i < N4X + N4W1)  { src = W1; dst = w1;  j = i - N4X; }
    else                      { src = W2; dst = w2;  j = i - N4X - N4W1; }
    float4 v = ((const float4*)src)[j];
    ((__half2*)dst)[j*2+0] = __floats2half2_rn(v.x, v.y);
    ((__half2*)dst)[j*2+1] = __floats2half2_rn(v.z, v.w);
}

// ---------------------------------------------------------------------------
// mma.sync helpers
// ---------------------------------------------------------------------------
__device__ __forceinline__ void ldsm_x4(uint32_t& r0, uint32_t& r1, uint32_t& r2, uint32_t& r3,
                                        uint32_t addr) {
    asm volatile("ldmatrix.sync.aligned.m8n8.x4.shared.b16 {%0,%1,%2,%3}, [%4];"
                 : "=r"(r0), "=r"(r1), "=r"(r2), "=r"(r3) : "r"(addr));
}
__device__ __forceinline__ void ldsm_x4_t(uint32_t& r0, uint32_t& r1, uint32_t& r2, uint32_t& r3,
                                          uint32_t addr) {
    asm volatile("ldmatrix.sync.aligned.m8n8.x4.trans.shared.b16 {%0,%1,%2,%3}, [%4];"
                 : "=r"(r0), "=r"(r1), "=r"(r2), "=r"(r3) : "r"(addr));
}
__device__ __forceinline__ void mma_f16(float* d, const uint32_t* a, uint32_t b0, uint32_t b1) {
    asm volatile(
        "mma.sync.aligned.m16n8k16.row.col.f32.f16.f16.f32 "
        "{%0,%1,%2,%3}, {%4,%5,%6,%7}, {%8,%9}, {%0,%1,%2,%3};"
        : "+f"(d[0]), "+f"(d[1]), "+f"(d[2]), "+f"(d[3])
        : "r"(a[0]), "r"(a[1]), "r"(a[2]), "r"(a[3]), "r"(b0), "r"(b1));
}
__device__ __forceinline__ uint32_t pack_hi2(float x, float y) {
    __half2 t = __floats2half2_rn(x, y);
    return *(uint32_t*)&t;
}
__device__ __forceinline__ float ex2f(float x) {
    float r;
    asm("ex2.approx.f32 %0, %1;" : "=f"(r) : "f"(x));
    return r;
}

// ---------------------------------------------------------------------------
// Persistent GEMM on mma.sync: C = A @ B + bias; A [M,K], B [K,N] (row-major,
// consumed via ldsm.trans). 128x128 tile, BK=64, cp.async double buffer
// continuous across tiles, 2 CTAs/SM.
// Columns [DD,2DD) scaled by QSCALE when writing fp16 Ch (Q pre-scale).
// ---------------------------------------------------------------------------
#define PA 72                 // A tile pitch: 128 rows(m) x 64 cols(k), +8 pad
#define PB 136                // B tile pitch: 64 rows(k) x 128 cols(n), +8 pad
#define ASZA (128 * PA)       // 9216 halfs
#define BSZB (64 * PB)        // 8704 halfs
#define STG (ASZA + BSZB)     // 17920 halfs per stage

__global__ __launch_bounds__(256, 2) void gemm_mma(
    const __half* __restrict__ Aa, const __half* __restrict__ Bw,
    const float* __restrict__ bias,
    float* __restrict__ C, __half* __restrict__ Ch,
    int M, int N, int K, int ntn)
{
    extern __shared__ __half sg[];   // 2 * STG
    const uint32_t uBase = smem_u32(sg);

    const int tid  = threadIdx.x;
    const int wid  = tid >> 5;
    const int lane = tid & 31;
    const int wrow = wid & 3;
    const int wcol = wid >> 2;

    const int a_row = wrow * 32 + (lane & 7) + ((lane >> 3) & 1) * 8;
    const int a_k   = (lane >> 4) * 8;
    const int b_kr  = lane & 15;
    const int b_nc  = (lane >> 4) * 8;

    const int ntiles  = (M >> 7) * ntn;
    const int nchunks = K >> 6;

    auto load_chunk = [&](int t, int kc, int buf) {
        const int m0 = (t / ntn) << 7;
        const int n0 = (t % ntn) << 7;
        const int k0 = kc << 6;
        const __half* gAk = Aa + (size_t)m0 * K + k0;
        const __half* gB  = Bw + (size_t)k0 * N + n0;
        const uint32_t sb = uBase + buf * (STG * 2);
#pragma unroll
        for (int v = tid; v < 2048; v += 256) {
            if (v < 1024) {
                int r = v >> 3, c = v & 7;                 // A: 128 rows x 8 vec
                cp16(sb + (r * PA + c * 8) * 2, gAk + (size_t)r * K + c * 8);
            } else {
                int idx = v - 1024;
                int r = idx >> 4, c = idx & 15;            // B: 64 rows x 16 vec
                cp16(sb + (ASZA + r * PB + c * 8) * 2, gB + (size_t)r * N + c * 8);
            }
        }
    };

    int lt = blockIdx.x, lk = 0;
    if (lt < ntiles) { load_chunk(lt, 0, 0); CP_COMMIT(); lk = 1; }
    int gbuf = 0;

    for (int tile = blockIdx.x; tile < ntiles; tile += gridDim.x) {
        float acc[2][8][4];
#pragma unroll
        for (int i = 0; i < 2; i++)
#pragma unroll
            for (int j = 0; j < 8; j++)
#pragma unroll
                for (int v = 0; v < 4; v++) acc[i][j][v] = 0.f;

        for (int kc = 0; kc < nchunks; ++kc) {
            CP_WAIT0();
            __syncthreads();
            if (lt < ntiles) {
                load_chunk(lt, lk, gbuf ^ 1);
                CP_COMMIT();
                if (++lk == nchunks) { lk = 0; lt += gridDim.x; }
            }
            const uint32_t s0 = uBase + gbuf * (STG * 2);
            const uint32_t tA = s0;
            const uint32_t tB = s0 + ASZA * 2;

#pragma unroll
            for (int ks = 0; ks < 4; ks++) {
                uint32_t ah[2][4];
#pragma unroll
                for (int mi = 0; mi < 2; mi++) {
                    uint32_t off = 2 * ((a_row + mi * 16) * PA + ks * 16 + a_k);
                    ldsm_x4(ah[mi][0], ah[mi][1], ah[mi][2], ah[mi][3], tA + off);
                }
#pragma unroll
                for (int j = 0; j < 4; j++) {
                    uint32_t off = 2 * ((ks * 16 + b_kr) * PB + wcol * 64 + j * 16 + b_nc);
                    uint32_t b0, b1, b2, b3;
                    ldsm_x4_t(b0, b1, b2, b3, tB + off);
#pragma unroll
                    for (int mi = 0; mi < 2; mi++) {
                        mma_f16(acc[mi][2*j],   ah[mi], b0, b1);
                        mma_f16(acc[mi][2*j+1], ah[mi], b2, b3);
                    }
                }
            }
            gbuf ^= 1;
        }

        // epilogue (next tile's chunk-0 load already in flight)
        const int m0 = (tile / ntn) << 7;
        const int n0 = (tile % ntn) << 7;
        const float qs = (Ch && n0 >= DD && n0 < 2 * DD) ? QSCALE : 1.0f;
        const int row0 = m0 + wrow * 32 + (lane >> 2);
        const int colb = n0 + wcol * 64 + (lane & 3) * 2;
#pragma unroll
        for (int mi = 0; mi < 2; mi++) {
#pragma unroll
            for (int nj = 0; nj < 8; nj++) {
                int c = colb + nj * 8;
                float2 bv = *(const float2*)(bias + c);
                float o00 = (acc[mi][nj][0] + bv.x) * qs, o01 = (acc[mi][nj][1] + bv.y) * qs;
                float o10 = (acc[mi][nj][2] + bv.x) * qs, o11 = (acc[mi][nj][3] + bv.y) * qs;
                size_t r0o = (size_t)(row0 + mi * 16) * N + c;
                size_t r1o = (size_t)(row0 + mi * 16 + 8) * N + c;
                if (Ch) {
                    *(uint32_t*)(Ch + r0o) = pack_hi2(o00, o01);
                    *(uint32_t*)(Ch + r1o) = pack_hi2(o10, o11);
                } else {
                    *(float2*)(C + r0o) = make_float2(o00, o01);
                    *(float2*)(C + r1o) = make_float2(o10, o11);
                }
            }
        }
    }
}

// ---------------------------------------------------------------------------
// Flash-attention, max-free softmax, with diagonal-tile work skipping:
// on the diagonal tile, warp w skips S-blocks ntp>w and PV chunks kc>w
// (all their p-values are exactly 0) — bit-exact, ~44% of diag-tile work.
// ---------------------------------------------------------------------------
#define PT 72
#define AT (128 * PT)
#define A_SMEM (5 * AT * 2)   // Q | 2 stages of (K|V) = 92160 B
#define ONES2 0x3C003C00u     // half2(1,1)

__global__ __launch_bounds__(256, 2) void attn_mma(
    const __half* __restrict__ ph, __half* __restrict__ oh)
{
    extern __shared__ __half sb[];
    const uint32_t uBase = smem_u32(sb);
    const uint32_t uQ = uBase;

    const int qb = gridDim.x - 1 - blockIdx.x;   // heavy blocks first
    const int bh = blockIdx.y;
    const int b = bh / HH, h = bh % HH;
    const int tid = threadIdx.x, w = tid >> 5, lane = tid & 31;
    const int quad = lane & 3, trow = lane >> 2;

    const size_t rowstride = 3 * DD;
    const size_t rbase = (size_t)b * SS * rowstride;
    const int koff = h * HD, qoff = DD + h * HD, voff = 2 * DD + h * HD;

    // Q copy: 128 rows x 8 uint4
#pragma unroll
    for (int i = tid; i < 1024; i += 256) {
        int r = i >> 3, c = i & 7;
        cp16(uBase + (r * PT + c * 8) * 2,
             ph + rbase + (size_t)(qb * 128 + r) * rowstride + qoff + c * 8);
    }

    auto load_kv = [&](int kb, int buf) {
        const uint32_t sbs = uBase + (AT + buf * 2 * AT) * 2;
#pragma unroll
        for (int i = tid; i < 2048; i += 256) {
            int t = i >> 10, idx = i & 1023;
            int r = idx >> 3, c = idx & 7;
            int off = t ? voff : koff;
            cp16(sbs + (t * AT + r * PT + c * 8) * 2,
                 ph + rbase + (size_t)(kb * 128 + r) * rowstride + off + c * 8);
        }
    };

    load_kv(0, 0);
    CP_COMMIT();

    float acc_o[8][4];
#pragma unroll
    for (int j = 0; j < 8; j++)
#pragma unroll
        for (int v = 0; v < 4; v++) acc_o[j][v] = 0.f;
    float acc_l[4] = {0.f, 0.f, 0.f, 0.f};

    for (int kb = 0; kb <= qb; ++kb) {
        const int buf = kb & 1;
        CP_WAIT0();
        __syncthreads();
        if (kb < qb) {
            load_kv(kb + 1, buf ^ 1);
            CP_COMMIT();
        }
        const uint32_t s0 = uBase + (AT + buf * 2 * AT) * 2;
        const uint32_t uK = s0, uV = s0 + AT * 2;
        const bool diag = (kb == qb);
        const int nlim = diag ? (w + 1) : 8;   // blocks beyond are fully masked

        // ---- S = Q' @ K^T (Q pre-scaled) ----
        float s[16][4];
#pragma unroll
        for (int j = 0; j < 16; j++)
#pragma unroll
            for (int v = 0; v < 4; v++) s[j][v] = 0.f;

#pragma unroll
        for (int kc = 0; kc < 4; kc++) {
            uint32_t qf[4];
            uint32_t aoff = 2 * ((w * 16 + (lane & 15)) * PT + kc * 16 + (lane >> 4) * 8);
            ldsm_x4(qf[0], qf[1], qf[2], qf[3], uQ + aoff);
#pragma unroll
            for (int ntp = 0; ntp < 8; ntp++) {
                if (ntp >= nlim) break;
                uint32_t boff = 2 * ((ntp * 16 + (lane & 15)) * PT + kc * 16 + (lane >> 4) * 8);
                uint32_t k0r, k1r, k2r, k3r;
                ldsm_x4(k0r, k1r, k2r, k3r, uK + boff);
                mma_f16(s[2*ntp],   qf, k0r, k2r);
                mma_f16(s[2*ntp+1], qf, k1r, k3r);
            }
        }

        // causal mask (diagonal block only)
        if (diag) {
            const int rl0 = w * 16 + trow;
#pragma unroll
            for (int nt = 0; nt < 16; nt++) {
                int c0 = nt * 8 + 2 * quad;
                if (c0 > rl0)     s[nt][0] = -1e30f;
                if (c0 + 1 > rl0) s[nt][1] = -1e30f;
                if (c0 > rl0 + 8)     s[nt][2] = -1e30f;
                if (c0 + 1 > rl0 + 8) s[nt][3] = -1e30f;
            }
        }

        // ---- p = 2^s ; O += P@V ; l += P@ones — fused per k-chunk ----
#pragma unroll
        for (int kc = 0; kc < 8; kc++) {
            if (kc >= nlim) break;   // diag: P rows beyond are exactly 0
            uint32_t pha[4];
            pha[0] = pack_hi2(ex2f(s[2*kc][0]),   ex2f(s[2*kc][1]));
            pha[1] = pack_hi2(ex2f(s[2*kc][2]),   ex2f(s[2*kc][3]));
            pha[2] = pack_hi2(ex2f(s[2*kc+1][0]), ex2f(s[2*kc+1][1]));
            pha[3] = pack_hi2(ex2f(s[2*kc+1][2]), ex2f(s[2*kc+1][3]));
            mma_f16(acc_l, pha, ONES2, ONES2);
#pragma unroll
            for (int ht = 0; ht < 4; ht++) {
                uint32_t v0, v1, v2, v3;
                uint32_t off = 2 * ((kc * 16 + (lane & 15)) * PT + ht * 16 + (lane >> 4) * 8);
                ldsm_x4_t(v0, v1, v2, v3, uV + off);
                mma_f16(acc_o[2*ht],   pha, v0, v1);
                mma_f16(acc_o[2*ht+1], pha, v2, v3);
            }
        }
    }

    // normalize and write fp16 output
    const float inv0 = 1.f / acc_l[0], inv1 = 1.f / acc_l[2];
    const size_t grow0 = (size_t)(b * SS + qb * 128 + w * 16 + trow);
    const size_t grow1 = grow0 + 8;
#pragma unroll
    for (int j = 0; j < 8; j++) {
        int c = h * HD + j * 8 + 2 * quad;
        *(uint32_t*)(oh + grow0 * DD + c) = pack_hi2(acc_o[j][0] * inv0, acc_o[j][1] * inv0);
        *(uint32_t*)(oh + grow1 * DD + c) = pack_hi2(acc_o[j][2] * inv1, acc_o[j][3] * inv1);
    }
}

// ---------------------------------------------------------------------------
extern "C" void kernel_launch(void* const* d_in, const int* in_sizes, int n_in,
                              void* d_out, int out_size)
{
    const float* x     = (const float*)d_in[0];
    const float* W_in  = (const float*)d_in[1];
    const float* b_in  = (const float*)d_in[2];
    const float* W_out = (const float*)d_in[3];
    const float* b_out = (const float*)d_in[4];
    float* out = (float*)d_out;

    __half *x16, *w1, *w2, *ph, *ah;
    cudaGetSymbolAddress((void**)&x16, g_x16);
    cudaGetSymbolAddress((void**)&w1, g_w1);
    cudaGetSymbolAddress((void**)&w2, g_w2);
    cudaGetSymbolAddress((void**)&ph, g_ph);
    cudaGetSymbolAddress((void**)&ah, g_ah);

    const int gemm_smem = 2 * STG * (int)sizeof(__half);   // 71680
    cudaFuncSetAttribute(gemm_mma, cudaFuncAttributeMaxDynamicSharedMemorySize, gemm_smem);
    cudaFuncSetAttribute(attn_mma, cudaFuncAttributeMaxDynamicSharedMemorySize, A_SMEM);

    // fused prep: x, W_in, W_out -> fp16
    conv_all<<<(N4ALL + 255) / 256, 256>>>(x, W_in, W_out, x16, w1, w2);

    // 1) QKV projection (grid == ntiles -> behaves exactly like R15)
    gemm_mma<<<BS / 128 * (3 * DD / 128), 256, gemm_smem>>>(
        x16, w1, b_in, nullptr, ph, BS, 3 * DD, DD, 3 * DD / 128);

    // 2) attention (max-free softmax, diag-skip) -> fp16 out
    {
        dim3 grid(SS / 128, BB * HH);
        attn_mma<<<grid, 256, A_SMEM>>>(ph, ah);
    }

    // 3) output projection — persistent: 512 tiles over 304 CTAs (2/SM),
    //    continuous pipeline removes the 1.68-wave quantization.
    gemm_mma<<<304, 256, gemm_smem>>>(
        ah, w2, b_out, out, nullptr, BS, DD, DD, DD / 128);
}

// round 17
// speedup vs baseline: 1.0397x; 1.0397x over previous
#include <cuda_runtime.h>
#include <cuda_fp16.h>
#include <cstdint>

// Problem constants
#define BB   4
#define SS   2048
#define DD   1024
#define HH   16
#define HD   64
#define BS   (BB*SS)        // 8192

__device__ __forceinline__ uint32_t smem_u32(const void* p) {
    uint32_t a;
    asm("{ .reg .u64 t; cvta.to.shared.u64 t, %1; cvt.u32.u64 %0, t; }" : "=r"(a) : "l"(p));
    return a;
}
__device__ __forceinline__ void cp16(uint32_t dst, const void* src) {
    asm volatile("cp.async.cg.shared.global [%0], [%1], 16;" :: "r"(dst), "l"(src));
}
#define CP_COMMIT() asm volatile("cp.async.commit_group;" ::: "memory")
#define CP_WAIT0()  asm volatile("cp.async.wait_group 0;" ::: "memory")

// 0.125 * log2(e): folded into Q at the GEMM1 epilogue
#define QSCALE 0.18033688011112042f

// ---------------------------------------------------------------------------
// Scratch (device globals)
// ---------------------------------------------------------------------------
__device__ __half g_x16[(size_t)BS * DD];      // x fp16
__device__ __half g_w1[(size_t)DD * (3*DD)];   // W_in  [1024,3072] fp16 row-major
__device__ __half g_w2[(size_t)DD * DD];       // W_out [1024,1024] fp16 row-major
__device__ __half g_ph[(size_t)BS * 3 * DD];   // proj (k|q|v) fp16, q pre-scaled
__device__ __half g_ah[(size_t)BS * DD];       // attention out fp16

// ---------------------------------------------------------------------------
// Fused prep: convert x, W_in, W_out to fp16 in one launch.
// ---------------------------------------------------------------------------
#define N4X  (BS * DD / 4)
#define N4W1 (DD * 3 * DD / 4)
#define N4W2 (DD * DD / 4)
#define N4ALL (N4X + N4W1 + N4W2)

__global__ __launch_bounds__(256) void conv_all(
    const float* __restrict__ x, const float* __restrict__ W1,
    const float* __restrict__ W2,
    __half* __restrict__ x16, __half* __restrict__ w1, __half* __restrict__ w2)
{
    int i = blockIdx.x * 256 + threadIdx.x;
    if (i >= N4ALL) return;
    const float* src;
    __half* dst;
    int j;
    if (i < N4X)              { src = x;  dst = x16; j = i; }
    else if (i < N4X + N4W1)  { src = W1; dst = w1;  j = i - N4X; }
    else                      { src = W2; dst = w2;  j = i - N4X - N4W1; }
    float4 v = ((const float4*)src)[j];
    ((__half2*)dst)[j*2+0] = __floats2half2_rn(v.x, v.y);
    ((__half2*)dst)[j*2+1] = __floats2half2_rn(v.z, v.w);
}

// ---------------------------------------------------------------------------
// mma.sync helpers
// ---------------------------------------------------------------------------
__device__ __forceinline__ void ldsm_x4(uint32_t& r0, uint32_t& r1, uint32_t& r2, uint32_t& r3,
                                        uint32_t addr) {
    asm volatile("ldmatrix.sync.aligned.m8n8.x4.shared.b16 {%0,%1,%2,%3}, [%4];"
                 : "=r"(r0), "=r"(r1), "=r"(r2), "=r"(r3) : "r"(addr));
}
__device__ __forceinline__ void ldsm_x4_t(uint32_t& r0, uint32_t& r1, uint32_t& r2, uint32_t& r3,
                                          uint32_t addr) {
    asm volatile("ldmatrix.sync.aligned.m8n8.x4.trans.shared.b16 {%0,%1,%2,%3}, [%4];"
                 : "=r"(r0), "=r"(r1), "=r"(r2), "=r"(r3) : "r"(addr));
}
__device__ __forceinline__ void mma_f16(float* d, const uint32_t* a, uint32_t b0, uint32_t b1) {
    asm volatile(
        "mma.sync.aligned.m16n8k16.row.col.f32.f16.f16.f32 "
        "{%0,%1,%2,%3}, {%4,%5,%6,%7}, {%8,%9}, {%0,%1,%2,%3};"
        : "+f"(d[0]), "+f"(d[1]), "+f"(d[2]), "+f"(d[3])
        : "r"(a[0]), "r"(a[1]), "r"(a[2]), "r"(a[3]), "r"(b0), "r"(b1));
}
__device__ __forceinline__ uint32_t pack_hi2(float x, float y) {
    __half2 t = __floats2half2_rn(x, y);
    return *(uint32_t*)&t;
}
__device__ __forceinline__ float ex2f(float x) {
    float r;
    asm("ex2.approx.f32 %0, %1;" : "=f"(r) : "f"(x));
    return r;
}

// ---------------------------------------------------------------------------
// Persistent GEMM: C = A @ B + bias; A [M,K], B [K,N] row-major (ldsm.trans).
// 128x128 tile, BK=64, cp.async double buffer continuous across tiles,
// 2 CTAs/SM. Tile coords cached per tile — NO division in the chunk loop.
// Columns [DD,2DD) scaled by QSCALE when writing fp16 Ch.
// ---------------------------------------------------------------------------
#define PA 72                 // A tile pitch
#define PB 136                // B tile pitch
#define ASZA (128 * PA)       // 9216 halfs
#define BSZB (64 * PB)        // 8704 halfs
#define STG (ASZA + BSZB)     // 17920 halfs per stage

__global__ __launch_bounds__(256, 2) void gemm_mma(
    const __half* __restrict__ Aa, const __half* __restrict__ Bw,
    const float* __restrict__ bias,
    float* __restrict__ C, __half* __restrict__ Ch,
    int M, int N, int K, int ntn)
{
    extern __shared__ __half sg[];   // 2 * STG
    const uint32_t uBase = smem_u32(sg);

    const int tid  = threadIdx.x;
    const int wid  = tid >> 5;
    const int lane = tid & 31;
    const int wrow = wid & 3;
    const int wcol = wid >> 2;

    const int a_row = wrow * 32 + (lane & 7) + ((lane >> 3) & 1) * 8;
    const int a_k   = (lane >> 4) * 8;
    const int b_kr  = lane & 15;
    const int b_nc  = (lane >> 4) * 8;

    const int ntiles  = (M >> 7) * ntn;
    const int nchunks = K >> 6;

    // loader uses pre-resolved tile coords (no division per chunk)
    auto load_chunk = [&](int m0, int n0, int kc, int buf) {
        const int k0 = kc << 6;
        const __half* gAk = Aa + (size_t)m0 * K + k0;
        const __half* gB  = Bw + (size_t)k0 * N + n0;
        const uint32_t sb = uBase + buf * (STG * 2);
#pragma unroll
        for (int v = tid; v < 2048; v += 256) {
            if (v < 1024) {
                int r = v >> 3, c = v & 7;
                cp16(sb + (r * PA + c * 8) * 2, gAk + (size_t)r * K + c * 8);
            } else {
                int idx = v - 1024;
                int r = idx >> 4, c = idx & 15;
                cp16(sb + (ASZA + r * PB + c * 8) * 2, gB + (size_t)r * N + c * 8);
            }
        }
    };

    // loader-side tile cursor (coords resolved once per tile)
    int lt = blockIdx.x, lk = 0;
    int lm0 = 0, ln0 = 0;
    if (lt < ntiles) {
        lm0 = (lt / ntn) << 7; ln0 = (lt % ntn) << 7;
        load_chunk(lm0, ln0, 0, 0);
        CP_COMMIT();
        lk = 1;
    }
    int gbuf = 0;

    for (int tile = blockIdx.x; tile < ntiles; tile += gridDim.x) {
        const int m0 = (tile / ntn) << 7;   // once per tile
        const int n0 = (tile % ntn) << 7;

        float acc[2][8][4];
#pragma unroll
        for (int i = 0; i < 2; i++)
#pragma unroll
            for (int j = 0; j < 8; j++)
#pragma unroll
                for (int v = 0; v < 4; v++) acc[i][j][v] = 0.f;

        for (int kc = 0; kc < nchunks; ++kc) {
            CP_WAIT0();
            __syncthreads();
            if (lt < ntiles) {
                load_chunk(lm0, ln0, lk, gbuf ^ 1);
                CP_COMMIT();
                if (++lk == nchunks) {
                    lk = 0;
                    lt += gridDim.x;
                    if (lt < ntiles) { lm0 = (lt / ntn) << 7; ln0 = (lt % ntn) << 7; }
                }
            }
            const uint32_t s0 = uBase + gbuf * (STG * 2);
            const uint32_t tA = s0;
            const uint32_t tB = s0 + ASZA * 2;

#pragma unroll
            for (int ks = 0; ks < 4; ks++) {
                uint32_t ah[2][4];
#pragma unroll
                for (int mi = 0; mi < 2; mi++) {
                    uint32_t off = 2 * ((a_row + mi * 16) * PA + ks * 16 + a_k);
                    ldsm_x4(ah[mi][0], ah[mi][1], ah[mi][2], ah[mi][3], tA + off);
                }
#pragma unroll
                for (int j = 0; j < 4; j++) {
                    uint32_t off = 2 * ((ks * 16 + b_kr) * PB + wcol * 64 + j * 16 + b_nc);
                    uint32_t b0, b1, b2, b3;
                    ldsm_x4_t(b0, b1, b2, b3, tB + off);
#pragma unroll
                    for (int mi = 0; mi < 2; mi++) {
                        mma_f16(acc[mi][2*j],   ah[mi], b0, b1);
                        mma_f16(acc[mi][2*j+1], ah[mi], b2, b3);
                    }
                }
            }
            gbuf ^= 1;
        }

        // epilogue (next tile's chunk-0 load already in flight)
        const float qs = (Ch && n0 >= DD && n0 < 2 * DD) ? QSCALE : 1.0f;
        const int row0 = m0 + wrow * 32 + (lane >> 2);
        const int colb = n0 + wcol * 64 + (lane & 3) * 2;
#pragma unroll
        for (int mi = 0; mi < 2; mi++) {
#pragma unroll
            for (int nj = 0; nj < 8; nj++) {
                int c = colb + nj * 8;
                float2 bv = *(const float2*)(bias + c);
                float o00 = (acc[mi][nj][0] + bv.x) * qs, o01 = (acc[mi][nj][1] + bv.y) * qs;
                float o10 = (acc[mi][nj][2] + bv.x) * qs, o11 = (acc[mi][nj][3] + bv.y) * qs;
                size_t r0o = (size_t)(row0 + mi * 16) * N + c;
                size_t r1o = (size_t)(row0 + mi * 16 + 8) * N + c;
                if (Ch) {
                    *(uint32_t*)(Ch + r0o) = pack_hi2(o00, o01);
                    *(uint32_t*)(Ch + r1o) = pack_hi2(o10, o11);
                } else {
                    *(float2*)(C + r0o) = make_float2(o00, o01);
                    *(float2*)(C + r1o) = make_float2(o10, o11);
                }
            }
        }
    }
}

// ---------------------------------------------------------------------------
// Flash-attention, max-free softmax (exact R15 structure):
//   Q pre-scaled by 0.125*log2e -> p = 2^s (ex2.approx), unnormalized.
//   l via ones-column MMA. Q/K/V/P single fp16. 2 CTAs/SM.
// ---------------------------------------------------------------------------
#define PT 72
#define AT (128 * PT)
#define A_SMEM (5 * AT * 2)   // Q | 2 stages of (K|V) = 92160 B
#define ONES2 0x3C003C00u     // half2(1,1)

__global__ __launch_bounds__(256, 2) void attn_mma(
    const __half* __restrict__ ph, __half* __restrict__ oh)
{
    extern __shared__ __half sb[];
    const uint32_t uBase = smem_u32(sb);
    const uint32_t uQ = uBase;

    const int qb = gridDim.x - 1 - blockIdx.x;   // heavy blocks first
    const int bh = blockIdx.y;
    const int b = bh / HH, h = bh % HH;
    const int tid = threadIdx.x, w = tid >> 5, lane = tid & 31;
    const int quad = lane & 3, trow = lane >> 2;

    const size_t rowstride = 3 * DD;
    const size_t rbase = (size_t)b * SS * rowstride;
    const int koff = h * HD, qoff = DD + h * HD, voff = 2 * DD + h * HD;

    // Q copy: 128 rows x 8 uint4
#pragma unroll
    for (int i = tid; i < 1024; i += 256) {
        int r = i >> 3, c = i & 7;
        cp16(uBase + (r * PT + c * 8) * 2,
             ph + rbase + (size_t)(qb * 128 + r) * rowstride + qoff + c * 8);
    }

    auto load_kv = [&](int kb, int buf) {
        const uint32_t sbs = uBase + (AT + buf * 2 * AT) * 2;
#pragma unroll
        for (int i = tid; i < 2048; i += 256) {
            int t = i >> 10, idx = i & 1023;
            int r = idx >> 3, c = idx & 7;
            int off = t ? voff : koff;
            cp16(sbs + (t * AT + r * PT + c * 8) * 2,
                 ph + rbase + (size_t)(kb * 128 + r) * rowstride + off + c * 8);
        }
    };

    load_kv(0, 0);
    CP_COMMIT();

    float acc_o[8][4];
#pragma unroll
    for (int j = 0; j < 8; j++)
#pragma unroll
        for (int v = 0; v < 4; v++) acc_o[j][v] = 0.f;
    float acc_l[4] = {0.f, 0.f, 0.f, 0.f};

    for (int kb = 0; kb <= qb; ++kb) {
        const int buf = kb & 1;
        CP_WAIT0();
        __syncthreads();
        if (kb < qb) {
            load_kv(kb + 1, buf ^ 1);
            CP_COMMIT();
        }
        const uint32_t s0 = uBase + (AT + buf * 2 * AT) * 2;
        const uint32_t uK = s0, uV = s0 + AT * 2;

        // ---- S = Q' @ K^T ----
        float s[16][4];
#pragma unroll
        for (int j = 0; j < 16; j++)
#pragma unroll
            for (int v = 0; v < 4; v++) s[j][v] = 0.f;

#pragma unroll
        for (int kc = 0; kc < 4; kc++) {
            uint32_t qf[4];
            uint32_t aoff = 2 * ((w * 16 + (lane & 15)) * PT + kc * 16 + (lane >> 4) * 8);
            ldsm_x4(qf[0], qf[1], qf[2], qf[3], uQ + aoff);
#pragma unroll
            for (int ntp = 0; ntp < 8; ntp++) {
                uint32_t boff = 2 * ((ntp * 16 + (lane & 15)) * PT + kc * 16 + (lane >> 4) * 8);
                uint32_t k0r, k1r, k2r, k3r;
                ldsm_x4(k0r, k1r, k2r, k3r, uK + boff);
                mma_f16(s[2*ntp],   qf, k0r, k2r);
                mma_f16(s[2*ntp+1], qf, k1r, k3r);
            }
        }

        // causal mask (diagonal block only)
        if (kb == qb) {
            const int rl0 = w * 16 + trow;
#pragma unroll
            for (int nt = 0; nt < 16; nt++) {
                int c0 = nt * 8 + 2 * quad;
                if (c0 > rl0)     s[nt][0] = -1e30f;
                if (c0 + 1 > rl0) s[nt][1] = -1e30f;
                if (c0 > rl0 + 8)     s[nt][2] = -1e30f;
                if (c0 + 1 > rl0 + 8) s[nt][3] = -1e30f;
            }
        }

        // ---- p = 2^s ; O += P@V ; l += P@ones — fused per k-chunk ----
#pragma unroll
        for (int kc = 0; kc < 8; kc++) {
            uint32_t pha[4];
            pha[0] = pack_hi2(ex2f(s[2*kc][0]),   ex2f(s[2*kc][1]));
            pha[1] = pack_hi2(ex2f(s[2*kc][2]),   ex2f(s[2*kc][3]));
            pha[2] = pack_hi2(ex2f(s[2*kc+1][0]), ex2f(s[2*kc+1][1]));
            pha[3] = pack_hi2(ex2f(s[2*kc+1][2]), ex2f(s[2*kc+1][3]));
            mma_f16(acc_l, pha, ONES2, ONES2);
#pragma unroll
            for (int ht = 0; ht < 4; ht++) {
                uint32_t v0, v1, v2, v3;
                uint32_t off = 2 * ((kc * 16 + (lane & 15)) * PT + ht * 16 + (lane >> 4) * 8);
                ldsm_x4_t(v0, v1, v2, v3, uV + off);
                mma_f16(acc_o[2*ht],   pha, v0, v1);
                mma_f16(acc_o[2*ht+1], pha, v2, v3);
            }
        }
    }

    // normalize and write fp16 output
    const float inv0 = 1.f / acc_l[0], inv1 = 1.f / acc_l[2];
    const size_t grow0 = (size_t)(b * SS + qb * 128 + w * 16 + trow);
    const size_t grow1 = grow0 + 8;
#pragma unroll
    for (int j = 0; j < 8; j++) {
        int c = h * HD + j * 8 + 2 * quad;
        *(uint32_t*)(oh + grow0 * DD + c) = pack_hi2(acc_o[j][0] * inv0, acc_o[j][1] * inv0);
        *(uint32_t*)(oh + grow1 * DD + c) = pack_hi2(acc_o[j][2] * inv1, acc_o[j][3] * inv1);
    }
}

// ---------------------------------------------------------------------------
extern "C" void kernel_launch(void* const* d_in, const int* in_sizes, int n_in,
                              void* d_out, int out_size)
{
    const float* x     = (const float*)d_in[0];
    const float* W_in  = (const float*)d_in[1];
    const float* b_in  = (const float*)d_in[2];
    const float* W_out = (const float*)d_in[3];
    const float* b_out = (const float*)d_in[4];
    float* out = (float*)d_out;

    __half *x16, *w1, *w2, *ph, *ah;
    cudaGetSymbolAddress((void**)&x16, g_x16);
    cudaGetSymbolAddress((void**)&w1, g_w1);
    cudaGetSymbolAddress((void**)&w2, g_w2);
    cudaGetSymbolAddress((void**)&ph, g_ph);
    cudaGetSymbolAddress((void**)&ah, g_ah);

    const int gemm_smem = 2 * STG * (int)sizeof(__half);   // 71680
    cudaFuncSetAttribute(gemm_mma, cudaFuncAttributeMaxDynamicSharedMemorySize, gemm_smem);
    cudaFuncSetAttribute(attn_mma, cudaFuncAttributeMaxDynamicSharedMemorySize, A_SMEM);

    // fused prep: x, W_in, W_out -> fp16
    conv_all<<<(N4ALL + 255) / 256, 256>>>(x, W_in, W_out, x16, w1, w2);

    // 1) QKV projection: grid == ntiles (one tile per CTA, R15 behavior)
    gemm_mma<<<(BS / 128) * (3 * DD / 128), 256, gemm_smem>>>(
        x16, w1, b_in, nullptr, ph, BS, 3 * DD, DD, 3 * DD / 128);

    // 2) attention (max-free softmax) -> fp16 out
    {
        dim3 grid(SS / 128, BB * HH);
        attn_mma<<<grid, 256, A_SMEM>>>(ph, ah);
    }

    // 3) output projection — persistent over 304 CTAs (2/SM), divisions
    //    hoisted per-tile: captures the 1.68-wave quantization loss.
    gemm_mma<<<304, 256, gemm_smem>>>(
        ah, w2, b_out, out, nullptr, BS, DD, DD, DD / 128);
}